// round 11
// baseline (speedup 1.0000x reference)
#include <cuda_runtime.h>
#include <cuda_fp16.h>
#include <cstdint>
#include <math.h>

// Problem: B=8, S=4096, D=1024, H=16, hd=64
#define MM 32768          // B*S
#define DD 1024
#define N_QKV 3072
#define NHEAD 16
#define HDIM 64
#define KK 1024

// GEMM tiling: single-pass fp16 (CTA 128x128, warp 64x32) — committed R10
#define BM 128
#define BN 128
#define BK 64
#define NCHUNK (KK / BK)      // 16
#define NSTAGE 3

#define OFF_A 0
#define OFF_B 16384
#define BUF_BYTES 32768
#define SMEM_DYN (NSTAGE * BUF_BYTES)     // 96 KB -> 2 CTAs/SM

// attention batching
#define TOK_PER_BLK 8

// ---------------------------------------------------------------------------
// Scratch (device globals)
// ---------------------------------------------------------------------------
__device__ __half g_qkvh[(size_t)MM * N_QKV];   // fp16 qkv
__device__ __half g_xh[(size_t)MM * DD];
__device__ __half g_wq[(size_t)N_QKV * KK];     // W_qkv^T  [N][K] fp16
__device__ __half g_wo[(size_t)DD * KK];        // W_out^T
__device__ __half g_vh[(size_t)MM * DD];

// ---------------------------------------------------------------------------
// Helpers
// ---------------------------------------------------------------------------
__device__ __forceinline__ uint32_t smem_u32(const void* p) {
    uint32_t a;
    asm("{ .reg .u64 t; cvta.to.shared.u64 t, %1; cvt.u32.u64 %0, t; }"
        : "=r"(a) : "l"(p));
    return a;
}

__device__ __forceinline__ void cp16(uint32_t dst, const void* src) {
    asm volatile("cp.async.cg.shared.global [%0], [%1], 16;"
                 :: "r"(dst), "l"(src) : "memory");
}
__device__ __forceinline__ void cp_commit() {
    asm volatile("cp.async.commit_group;" ::: "memory");
}
template <int N>
__device__ __forceinline__ void cp_wait() {
    asm volatile("cp.async.wait_group %0;" :: "n"(N) : "memory");
}

#define LDX4(r, addr) \
    asm volatile("ldmatrix.sync.aligned.m8n8.x4.shared.b16 {%0,%1,%2,%3}, [%4];" \
        : "=r"((r)[0]), "=r"((r)[1]), "=r"((r)[2]), "=r"((r)[3]) : "r"(addr))

#define MMA16816(d, a, b) \
    asm volatile("mma.sync.aligned.m16n8k16.row.col.f32.f16.f16.f32 " \
        "{%0,%1,%2,%3}, {%4,%5,%6,%7}, {%8,%9}, {%0,%1,%2,%3};" \
        : "+f"((d)[0]), "+f"((d)[1]), "+f"((d)[2]), "+f"((d)[3]) \
        : "r"((a)[0]), "r"((a)[1]), "r"((a)[2]), "r"((a)[3]), \
          "r"((b)[0]), "r"((b)[1]))

// ---------------------------------------------------------------------------
// HMMA GEMM (single-pass fp16): C[M,Ntot] = A[M,K] @ B[Ntot,K]^T + bias
// fp32 accum, OutT output. CTA 128x128, warp 64x32 (2m x 4n), BK=64, SW128,
// 3-stage cp.async, 2 CTAs/SM, ONE __syncthreads per chunk. (R10 committed)
// ---------------------------------------------------------------------------
template <typename OutT>
__global__ __launch_bounds__(256, 2)
void gemm_hmma(const __half* __restrict__ Am, const __half* __restrict__ Bm,
               const float* __restrict__ bias, OutT* __restrict__ C, int Ntot)
{
    extern __shared__ char smem[];
    const uint32_t sb = smem_u32(smem);

    const int tid  = threadIdx.x;
    const int wid  = tid >> 5;
    const int lane = tid & 31;
    const int wm = (wid & 1) * 64;
    const int wn = (wid >> 1) * 32;

    const size_t m0 = (size_t)blockIdx.y * BM;
    const size_t n0 = (size_t)blockIdx.x * BN;

    const __half* srcA[4];
    const __half* srcB[4];
    uint32_t dstOff[4];
    #pragma unroll
    for (int t = 0; t < 4; t++) {
        int idx = tid + t * 256;
        int row = idx >> 3;
        int cq  = idx & 7;
        srcA[t] = Am + (m0 + row) * KK + cq * 8;
        srcB[t] = Bm + (n0 + row) * KK + cq * 8;
        dstOff[t] = row * 128 + ((cq * 16) ^ ((row & 7) << 4));   // SW128
    }

    uint32_t offA[4], offB[2];
    #pragma unroll
    for (int tm = 0; tm < 4; tm++) {
        int row = wm + tm * 16 + (lane & 15);
        offA[tm] = row * 128 + ((((lane >> 4) << 4)) ^ ((row & 7) << 4));
    }
    #pragma unroll
    for (int tp = 0; tp < 2; tp++) {
        int row = wn + tp * 16 + ((lane >> 4) & 1) * 8 + (lane & 7);
        offB[tp] = row * 128 + ((((lane >> 3) & 1) * 16) ^ ((row & 7) << 4));
    }

    float acc[4][4][4];
    #pragma unroll
    for (int i = 0; i < 4; i++)
        #pragma unroll
        for (int j = 0; j < 4; j++)
            #pragma unroll
            for (int r = 0; r < 4; r++) acc[i][j][r] = 0.0f;

    #pragma unroll
    for (int s = 0; s < 2; s++) {
        const uint32_t buf = sb + s * BUF_BYTES;
        const int koff = s * BK;
        #pragma unroll
        for (int t = 0; t < 4; t++) {
            cp16(buf + OFF_A + dstOff[t], srcA[t] + koff);
            cp16(buf + OFF_B + dstOff[t], srcB[t] + koff);
        }
        cp_commit();
    }

    int bufIdx = 0;
    #pragma unroll 1
    for (int c = 0; c < NCHUNK; ++c) {
        cp_wait<1>();
        __syncthreads();

        if (c + 2 < NCHUNK) {
            int pidx = bufIdx + 2; if (pidx >= NSTAGE) pidx -= NSTAGE;
            const uint32_t nbuf = sb + pidx * BUF_BYTES;
            const int koff = (c + 2) * BK;
            #pragma unroll
            for (int t = 0; t < 4; t++) {
                cp16(nbuf + OFF_A + dstOff[t], srcA[t] + koff);
                cp16(nbuf + OFF_B + dstOff[t], srcB[t] + koff);
            }
        }
        cp_commit();

        const uint32_t buf = sb + bufIdx * BUF_BYTES;
        #pragma unroll
        for (int ks = 0; ks < 4; ks++) {
            const uint32_t kx = ks * 32;
            uint32_t aa[4][4], bb[4][2];

            #pragma unroll
            for (int tm = 0; tm < 4; tm++)
                LDX4(aa[tm], buf + OFF_A + (offA[tm] ^ kx));
            #pragma unroll
            for (int tp = 0; tp < 2; tp++) {
                uint32_t r[4];
                LDX4(r, buf + OFF_B + (offB[tp] ^ kx));
                bb[2 * tp][0] = r[0]; bb[2 * tp][1] = r[1];
                bb[2 * tp + 1][0] = r[2]; bb[2 * tp + 1][1] = r[3];
            }
            #pragma unroll
            for (int tm = 0; tm < 4; tm++)
                #pragma unroll
                for (int tn = 0; tn < 4; tn++)
                    MMA16816(acc[tm][tn], aa[tm], bb[tn]);
        }
        if (++bufIdx == NSTAGE) bufIdx = 0;
    }

    const int rq = lane >> 2;
    const int cp = (lane & 3) * 2;
    #pragma unroll
    for (int tn = 0; tn < 4; tn++) {
        const int col = (int)n0 + wn + tn * 8 + cp;
        const float b0 = bias[col], b1 = bias[col + 1];
        #pragma unroll
        for (int tm = 0; tm < 4; tm++) {
            const size_t r1 = m0 + wm + tm * 16 + rq;
            float2 o0, o1;
            o0.x = acc[tm][tn][0] + b0;
            o0.y = acc[tm][tn][1] + b1;
            o1.x = acc[tm][tn][2] + b0;
            o1.y = acc[tm][tn][3] + b1;
            if constexpr (sizeof(OutT) == 4) {
                *reinterpret_cast<float2*>((float*)C + r1 * Ntot + col) = o0;
                *reinterpret_cast<float2*>((float*)C + (r1 + 8) * Ntot + col) = o1;
            } else {
                *reinterpret_cast<__half2*>((__half*)C + r1 * Ntot + col) =
                    __floats2half2_rn(o0.x, o0.y);
                *reinterpret_cast<__half2*>((__half*)C + (r1 + 8) * Ntot + col) =
                    __floats2half2_rn(o1.x, o1.y);
            }
        }
    }
}

// ---------------------------------------------------------------------------
// fp32 -> fp16 convert (x)
// ---------------------------------------------------------------------------
__global__ __launch_bounds__(256)
void conv_h(const float* __restrict__ in, __half* __restrict__ hi)
{
    size_t i0 = ((size_t)blockIdx.x * 256 + threadIdx.x) * 4;
    float4 v = *reinterpret_cast<const float4*>(in + i0);
    __half2 a, b;
    a.x = __float2half_rn(v.x); a.y = __float2half_rn(v.y);
    b.x = __float2half_rn(v.z); b.y = __float2half_rn(v.w);
    reinterpret_cast<__half2*>(hi + i0)[0] = a;
    reinterpret_cast<__half2*>(hi + i0)[1] = b;
}

// ---------------------------------------------------------------------------
// W[K][N] fp32 -> W^T[N][K] fp16, tiled & coalesced
// ---------------------------------------------------------------------------
__global__ __launch_bounds__(256)
void transpose_h(const float* __restrict__ W, __half* __restrict__ WT, int N)
{
    __shared__ float tile[32][33];
    const int k0 = blockIdx.x * 32;
    const int n0 = blockIdx.y * 32;
    const int tx = threadIdx.x, ty = threadIdx.y;
    #pragma unroll
    for (int j = 0; j < 4; j++)
        tile[ty + j * 8][tx] = W[(size_t)(k0 + ty + j * 8) * N + n0 + tx];
    __syncthreads();
    #pragma unroll
    for (int j = 0; j < 4; j++)
        WT[(size_t)(n0 + ty + j * 8) * KK + k0 + tx] =
            __float2half_rn(tile[tx][ty + j * 8]);
}

// ---------------------------------------------------------------------------
// Per-token 16x16 head attention, batched: TOK_PER_BLK tokens per block,
// next token's raw qkv row (6 KB) prefetched via cp.async (ping-pong smem)
// while the current token computes. Per-token math identical to R10.
// ---------------------------------------------------------------------------
__global__ __launch_bounds__(256)
void attn_kernel()
{
    __shared__ __align__(16) __half rawq[2][N_QKV];   // 2 x 6 KB
    __shared__ float sq[NHEAD][HDIM];
    __shared__ float skT[HDIM][NHEAD + 1];
    __shared__ float sv[NHEAD][HDIM];
    __shared__ float sat[NHEAD][NHEAD];

    const int tid = threadIdx.x;
    const size_t p0 = (size_t)blockIdx.x * TOK_PER_BLK;
    const uint32_t raw_s[2] = { smem_u32(&rawq[0][0]), smem_u32(&rawq[1][0]) };

    // prefetch token 0: 6144 B = 384 x16B chunks, 256 threads
    {
        const char* src = (const char*)(g_qkvh + p0 * N_QKV);
        cp16(raw_s[0] + tid * 16, src + tid * 16);
        if (tid < 128) cp16(raw_s[0] + (tid + 256) * 16, src + (tid + 256) * 16);
        cp_commit();
    }

    #pragma unroll 1
    for (int t = 0; t < TOK_PER_BLK; ++t) {
        // prefetch next token
        if (t + 1 < TOK_PER_BLK) {
            const char* src = (const char*)(g_qkvh + (p0 + t + 1) * N_QKV);
            const uint32_t dst = raw_s[(t + 1) & 1];
            cp16(dst + tid * 16, src + tid * 16);
            if (tid < 128) cp16(dst + (tid + 256) * 16, src + (tid + 256) * 16);
        }
        cp_commit();
        cp_wait<1>();
        __syncthreads();

        // scatter raw -> sq / skT / sv (identical values & layout to R10)
        const __half2* row2 = reinterpret_cast<const __half2*>(&rawq[t & 1][0]);
        #pragma unroll
        for (int u = 0; u < 6; u++) {
            int i2 = tid + u * 256;
            float2 f = __half22float2(row2[i2]);
            int h = i2 / 96;
            int r = 2 * (i2 - h * 96);
            if (r < 64) {
                sq[h][r] = f.x; sq[h][r + 1] = f.y;
            } else if (r < 128) {
                int rr = r - 64;
                skT[rr][h] = f.x; skT[rr + 1][h] = f.y;
            } else {
                int rr = r - 128;
                sv[h][rr] = f.x; sv[h][rr + 1] = f.y;
            }
        }
        __syncthreads();

        const int i = tid >> 4;
        const int j = tid & 15;
        float s = 0.0f;
        #pragma unroll 8
        for (int d = 0; d < HDIM; d++) s += sq[i][d] * skT[d][j];
        s *= 0.125f;

        float mx = s;
        #pragma unroll
        for (int m = 8; m >= 1; m >>= 1)
            mx = fmaxf(mx, __shfl_xor_sync(0xffffffffu, mx, m));
        float e = __expf(s - mx);
        float sum = e;
        #pragma unroll
        for (int m = 8; m >= 1; m >>= 1)
            sum += __shfl_xor_sync(0xffffffffu, sum, m);
        sat[i][j] = e / sum;
        __syncthreads();

        __half2* vh2 = reinterpret_cast<__half2*>(g_vh + (p0 + t) * (size_t)DD);
        #pragma unroll
        for (int u = 0; u < 2; u++) {
            int i2 = tid + u * 256;
            int oi = i2 >> 5;
            int d  = (i2 & 31) * 2;
            float a0 = 0.0f, a1 = 0.0f;
            #pragma unroll
            for (int jj = 0; jj < NHEAD; jj++) {
                float w = sat[oi][jj];
                a0 += w * sv[jj][d];
                a1 += w * sv[jj][d + 1];
            }
            vh2[i2] = __floats2half2_rn(a0, a1);
        }
        __syncthreads();   // staging reused next iteration
    }
}

// ---------------------------------------------------------------------------
// Launch: x, W_qkv, b_qkv, W_out, b_out
// ---------------------------------------------------------------------------
extern "C" void kernel_launch(void* const* d_in, const int* in_sizes, int n_in,
                              void* d_out, int out_size)
{
    const float* x     = (const float*)d_in[0];
    const float* W_qkv = (const float*)d_in[1];
    const float* b_qkv = (const float*)d_in[2];
    const float* W_out = (const float*)d_in[3];
    const float* b_out = (const float*)d_in[4];
    float* out = (float*)d_out;

    __half *qkvh, *xh, *wq, *wo, *vh;
    cudaGetSymbolAddress((void**)&qkvh, g_qkvh);
    cudaGetSymbolAddress((void**)&xh, g_xh);
    cudaGetSymbolAddress((void**)&wq, g_wq);
    cudaGetSymbolAddress((void**)&wo, g_wo);
    cudaGetSymbolAddress((void**)&vh, g_vh);

    cudaFuncSetAttribute(gemm_hmma<__half>,
                         cudaFuncAttributeMaxDynamicSharedMemorySize, SMEM_DYN);
    cudaFuncSetAttribute(gemm_hmma<float>,
                         cudaFuncAttributeMaxDynamicSharedMemorySize, SMEM_DYN);

    // conversions
    conv_h<<<(size_t)MM * DD / (256 * 4), 256>>>(x, xh);
    transpose_h<<<dim3(KK / 32, N_QKV / 32), dim3(32, 8)>>>(W_qkv, wq, N_QKV);
    transpose_h<<<dim3(KK / 32, DD / 32), dim3(32, 8)>>>(W_out, wo, DD);

    // GEMM1: qkv(fp16) = x @ W_qkv + b_qkv   (32768 x 3072, K=1024)
    gemm_hmma<__half><<<dim3(N_QKV / BN, MM / BM), 256, SMEM_DYN>>>(
        xh, wq, b_qkv, qkvh, N_QKV);

    // attention, 8 tokens per block
    attn_kernel<<<MM / TOK_PER_BLK, 256>>>();

    // GEMM2: out = val @ W_out + b_out (32768 x 1024, K=1024)
    gemm_hmma<float><<<dim3(DD / BN, MM / BM), 256, SMEM_DYN>>>(
        vh, wo, b_out, out, DD);
}

// round 14
// speedup vs baseline: 1.7841x; 1.7841x over previous
#include <cuda_runtime.h>
#include <cuda_fp16.h>
#include <cstdint>
#include <math.h>

// Problem: B=8, S=4096, D=1024, H=16, hd=64
#define MM 32768          // B*S
#define DD 1024
#define N_QKV 3072
#define NHEAD 16
#define HDIM 64
#define KK 1024

// GEMM tiling: single-pass fp16 (CTA 128x128, warp 64x32) — committed R10
#define BM 128
#define BN 128
#define BK 64
#define NCHUNK (KK / BK)      // 16
#define NSTAGE 3

#define OFF_A 0
#define OFF_B 16384
#define BUF_BYTES 32768
#define SMEM_DYN (NSTAGE * BUF_BYTES)     // 96 KB -> 2 CTAs/SM

// attention staging: per-warp 3x1024 halfs + 32-half pad (bank decorrelation,
// and keeps total static smem at 46.5 KB, under the 48 KB static limit)
#define AT_WSTRIDE (3 * NHEAD * HDIM + 32)

// ---------------------------------------------------------------------------
// Scratch (device globals)
// ---------------------------------------------------------------------------
__device__ __half g_qkvh[(size_t)MM * N_QKV];   // fp16 qkv
__device__ __half g_xh[(size_t)MM * DD];
__device__ __half g_wq[(size_t)N_QKV * KK];     // W_qkv^T  [N][K] fp16
__device__ __half g_wo[(size_t)DD * KK];        // W_out^T
__device__ __half g_vh[(size_t)MM * DD];

// ---------------------------------------------------------------------------
// Helpers
// ---------------------------------------------------------------------------
__device__ __forceinline__ uint32_t smem_u32(const void* p) {
    uint32_t a;
    asm("{ .reg .u64 t; cvta.to.shared.u64 t, %1; cvt.u32.u64 %0, t; }"
        : "=r"(a) : "l"(p));
    return a;
}

__device__ __forceinline__ void cp16(uint32_t dst, const void* src) {
    asm volatile("cp.async.cg.shared.global [%0], [%1], 16;"
                 :: "r"(dst), "l"(src) : "memory");
}
__device__ __forceinline__ void cp_commit() {
    asm volatile("cp.async.commit_group;" ::: "memory");
}
template <int N>
__device__ __forceinline__ void cp_wait() {
    asm volatile("cp.async.wait_group %0;" :: "n"(N) : "memory");
}

#define LDX4(r, addr) \
    asm volatile("ldmatrix.sync.aligned.m8n8.x4.shared.b16 {%0,%1,%2,%3}, [%4];" \
        : "=r"((r)[0]), "=r"((r)[1]), "=r"((r)[2]), "=r"((r)[3]) : "r"(addr))

#define LDX4T(r, addr) \
    asm volatile("ldmatrix.sync.aligned.m8n8.x4.trans.shared.b16 {%0,%1,%2,%3}, [%4];" \
        : "=r"((r)[0]), "=r"((r)[1]), "=r"((r)[2]), "=r"((r)[3]) : "r"(addr))

#define MMA16816(d, a, b) \
    asm volatile("mma.sync.aligned.m16n8k16.row.col.f32.f16.f16.f32 " \
        "{%0,%1,%2,%3}, {%4,%5,%6,%7}, {%8,%9}, {%0,%1,%2,%3};" \
        : "+f"((d)[0]), "+f"((d)[1]), "+f"((d)[2]), "+f"((d)[3]) \
        : "r"((a)[0]), "r"((a)[1]), "r"((a)[2]), "r"((a)[3]), \
          "r"((b)[0]), "r"((b)[1]))

// ---------------------------------------------------------------------------
// HMMA GEMM (single-pass fp16): C[M,Ntot] = A[M,K] @ B[Ntot,K]^T + bias
// fp32 accum, OutT output. CTA 128x128, warp 64x32 (2m x 4n), BK=64, SW128,
// 3-stage cp.async, 2 CTAs/SM, ONE __syncthreads per chunk. (R10 committed)
// ---------------------------------------------------------------------------
template <typename OutT>
__global__ __launch_bounds__(256, 2)
void gemm_hmma(const __half* __restrict__ Am, const __half* __restrict__ Bm,
               const float* __restrict__ bias, OutT* __restrict__ C, int Ntot)
{
    extern __shared__ char smem[];
    const uint32_t sb = smem_u32(smem);

    const int tid  = threadIdx.x;
    const int wid  = tid >> 5;
    const int lane = tid & 31;
    const int wm = (wid & 1) * 64;
    const int wn = (wid >> 1) * 32;

    const size_t m0 = (size_t)blockIdx.y * BM;
    const size_t n0 = (size_t)blockIdx.x * BN;

    const __half* srcA[4];
    const __half* srcB[4];
    uint32_t dstOff[4];
    #pragma unroll
    for (int t = 0; t < 4; t++) {
        int idx = tid + t * 256;
        int row = idx >> 3;
        int cq  = idx & 7;
        srcA[t] = Am + (m0 + row) * KK + cq * 8;
        srcB[t] = Bm + (n0 + row) * KK + cq * 8;
        dstOff[t] = row * 128 + ((cq * 16) ^ ((row & 7) << 4));   // SW128
    }

    uint32_t offA[4], offB[2];
    #pragma unroll
    for (int tm = 0; tm < 4; tm++) {
        int row = wm + tm * 16 + (lane & 15);
        offA[tm] = row * 128 + ((((lane >> 4) << 4)) ^ ((row & 7) << 4));
    }
    #pragma unroll
    for (int tp = 0; tp < 2; tp++) {
        int row = wn + tp * 16 + ((lane >> 4) & 1) * 8 + (lane & 7);
        offB[tp] = row * 128 + ((((lane >> 3) & 1) * 16) ^ ((row & 7) << 4));
    }

    float acc[4][4][4];
    #pragma unroll
    for (int i = 0; i < 4; i++)
        #pragma unroll
        for (int j = 0; j < 4; j++)
            #pragma unroll
            for (int r = 0; r < 4; r++) acc[i][j][r] = 0.0f;

    #pragma unroll
    for (int s = 0; s < 2; s++) {
        const uint32_t buf = sb + s * BUF_BYTES;
        const int koff = s * BK;
        #pragma unroll
        for (int t = 0; t < 4; t++) {
            cp16(buf + OFF_A + dstOff[t], srcA[t] + koff);
            cp16(buf + OFF_B + dstOff[t], srcB[t] + koff);
        }
        cp_commit();
    }

    int bufIdx = 0;
    #pragma unroll 1
    for (int c = 0; c < NCHUNK; ++c) {
        cp_wait<1>();
        __syncthreads();

        if (c + 2 < NCHUNK) {
            int pidx = bufIdx + 2; if (pidx >= NSTAGE) pidx -= NSTAGE;
            const uint32_t nbuf = sb + pidx * BUF_BYTES;
            const int koff = (c + 2) * BK;
            #pragma unroll
            for (int t = 0; t < 4; t++) {
                cp16(nbuf + OFF_A + dstOff[t], srcA[t] + koff);
                cp16(nbuf + OFF_B + dstOff[t], srcB[t] + koff);
            }
        }
        cp_commit();

        const uint32_t buf = sb + bufIdx * BUF_BYTES;
        #pragma unroll
        for (int ks = 0; ks < 4; ks++) {
            const uint32_t kx = ks * 32;
            uint32_t aa[4][4], bb[4][2];

            #pragma unroll
            for (int tm = 0; tm < 4; tm++)
                LDX4(aa[tm], buf + OFF_A + (offA[tm] ^ kx));
            #pragma unroll
            for (int tp = 0; tp < 2; tp++) {
                uint32_t r[4];
                LDX4(r, buf + OFF_B + (offB[tp] ^ kx));
                bb[2 * tp][0] = r[0]; bb[2 * tp][1] = r[1];
                bb[2 * tp + 1][0] = r[2]; bb[2 * tp + 1][1] = r[3];
            }
            #pragma unroll
            for (int tm = 0; tm < 4; tm++)
                #pragma unroll
                for (int tn = 0; tn < 4; tn++)
                    MMA16816(acc[tm][tn], aa[tm], bb[tn]);
        }
        if (++bufIdx == NSTAGE) bufIdx = 0;
    }

    const int rq = lane >> 2;
    const int cp = (lane & 3) * 2;
    #pragma unroll
    for (int tn = 0; tn < 4; tn++) {
        const int col = (int)n0 + wn + tn * 8 + cp;
        const float b0 = bias[col], b1 = bias[col + 1];
        #pragma unroll
        for (int tm = 0; tm < 4; tm++) {
            const size_t r1 = m0 + wm + tm * 16 + rq;
            float2 o0, o1;
            o0.x = acc[tm][tn][0] + b0;
            o0.y = acc[tm][tn][1] + b1;
            o1.x = acc[tm][tn][2] + b0;
            o1.y = acc[tm][tn][3] + b1;
            if constexpr (sizeof(OutT) == 4) {
                *reinterpret_cast<float2*>((float*)C + r1 * Ntot + col) = o0;
                *reinterpret_cast<float2*>((float*)C + (r1 + 8) * Ntot + col) = o1;
            } else {
                *reinterpret_cast<__half2*>((__half*)C + r1 * Ntot + col) =
                    __floats2half2_rn(o0.x, o0.y);
                *reinterpret_cast<__half2*>((__half*)C + (r1 + 8) * Ntot + col) =
                    __floats2half2_rn(o1.x, o1.y);
            }
        }
    }
}

// ---------------------------------------------------------------------------
// fp32 -> fp16 convert (x)
// ---------------------------------------------------------------------------
__global__ __launch_bounds__(256)
void conv_h(const float* __restrict__ in, __half* __restrict__ hi)
{
    size_t i0 = ((size_t)blockIdx.x * 256 + threadIdx.x) * 4;
    float4 v = *reinterpret_cast<const float4*>(in + i0);
    __half2 a, b;
    a.x = __float2half_rn(v.x); a.y = __float2half_rn(v.y);
    b.x = __float2half_rn(v.z); b.y = __float2half_rn(v.w);
    reinterpret_cast<__half2*>(hi + i0)[0] = a;
    reinterpret_cast<__half2*>(hi + i0)[1] = b;
}

// ---------------------------------------------------------------------------
// W[K][N] fp32 -> W^T[N][K] fp16, tiled & coalesced
// ---------------------------------------------------------------------------
__global__ __launch_bounds__(256)
void transpose_h(const float* __restrict__ W, __half* __restrict__ WT, int N)
{
    __shared__ float tile[32][33];
    const int k0 = blockIdx.x * 32;
    const int n0 = blockIdx.y * 32;
    const int tx = threadIdx.x, ty = threadIdx.y;
    #pragma unroll
    for (int j = 0; j < 4; j++)
        tile[ty + j * 8][tx] = W[(size_t)(k0 + ty + j * 8) * N + n0 + tx];
    __syncthreads();
    #pragma unroll
    for (int j = 0; j < 4; j++)
        WT[(size_t)(n0 + ty + j * 8) * KK + k0 + tx] =
            __float2half_rn(tile[tx][ty + j * 8]);
}

// ---------------------------------------------------------------------------
// Per-token 16x16 head attention via tensor cores. ONE WARP PER TOKEN.
// S(16x16) = Q K^T via 8x m16n8k16; fragment softmax; O(16x64) = P V via
// 8x m16n8k16 with ldmatrix.trans for V. No block barriers.
// ---------------------------------------------------------------------------
__global__ __launch_bounds__(256)
void attn_kernel()
{
    __shared__ __align__(16) __half stage[8 * AT_WSTRIDE];   // 46.5 KB

    const int tid  = threadIdx.x;
    const int wid  = tid >> 5;
    const int lane = tid & 31;
    const size_t p = (size_t)blockIdx.x * 8 + wid;

    const uint32_t wb = smem_u32(&stage[wid * AT_WSTRIDE]);  // q | k | v, 2KB each
    // 16 rows x 128B per section, chunks swizzled by (row&7)<<4

    // ---- stage token row (3072 halfs = 384 x16B chunks, 12/lane) ----
    {
        const int4* src = reinterpret_cast<const int4*>(g_qkvh + p * N_QKV);
        #pragma unroll
        for (int t = 0; t < 12; t++) {
            int c  = lane + t * 32;
            int h  = c / 24;                  // head
            int cc = c - h * 24;              // chunk within head (24 = 3*8)
            int sec = cc >> 3;                // 0=q 1=k 2=v
            int dc  = cc & 7;                 // 16B chunk within 128B row
            uint32_t dst = wb + sec * 2048 + h * 128
                         + (((uint32_t)dc << 4) ^ ((h & 7) << 4));
            int4 v = src[c];
            asm volatile("st.shared.v4.b32 [%0], {%1,%2,%3,%4};"
                :: "r"(dst), "r"(v.x), "r"(v.y), "r"(v.z), "r"(v.w) : "memory");
        }
    }
    __syncwarp();

    const uint32_t qb = wb, kb = wb + 2048, vb = wb + 4096;

    // ---- S = Q K^T  (two n-tiles of 8 j's, 4 k-chunks of 16 dims) ----
    float s0[4] = {0.f, 0.f, 0.f, 0.f};      // j 0-7
    float s1[4] = {0.f, 0.f, 0.f, 0.f};      // j 8-15
    {
        const int ia = lane & 15;                       // Q row (head i)
        const uint32_t ca = (uint32_t)(lane >> 4);      // A k-half chunk
        const int jb = (lane & 7) + ((lane >> 4) << 3); // K row (head j)
        const uint32_t cb = (uint32_t)((lane >> 3) & 1);
        #pragma unroll
        for (int kc = 0; kc < 4; kc++) {
            uint32_t aa[4], bb[4];
            LDX4(aa, qb + ia * 128 +
                 ((((uint32_t)(kc * 2) + ca) << 4) ^ ((ia & 7) << 4)));
            LDX4(bb, kb + jb * 128 +
                 ((((uint32_t)(kc * 2) + cb) << 4) ^ ((jb & 7) << 4)));
            MMA16816(s0, aa, bb);
            MMA16816(s1, aa, bb + 2);
        }
    }

    // ---- fragment softmax (rows gid and gid+8; quad = lanes with same gid)
    #pragma unroll
    for (int r = 0; r < 4; r++) { s0[r] *= 0.125f; s1[r] *= 0.125f; }

    float m0 = fmaxf(fmaxf(s0[0], s0[1]), fmaxf(s1[0], s1[1]));
    float m1 = fmaxf(fmaxf(s0[2], s0[3]), fmaxf(s1[2], s1[3]));
    m0 = fmaxf(m0, __shfl_xor_sync(0xffffffffu, m0, 1));
    m0 = fmaxf(m0, __shfl_xor_sync(0xffffffffu, m0, 2));
    m1 = fmaxf(m1, __shfl_xor_sync(0xffffffffu, m1, 1));
    m1 = fmaxf(m1, __shfl_xor_sync(0xffffffffu, m1, 2));

    float e00 = __expf(s0[0] - m0), e01 = __expf(s0[1] - m0);
    float e10 = __expf(s1[0] - m0), e11 = __expf(s1[1] - m0);
    float e02 = __expf(s0[2] - m1), e03 = __expf(s0[3] - m1);
    float e12 = __expf(s1[2] - m1), e13 = __expf(s1[3] - m1);

    float sum0 = e00 + e01 + e10 + e11;
    float sum1 = e02 + e03 + e12 + e13;
    sum0 += __shfl_xor_sync(0xffffffffu, sum0, 1);
    sum0 += __shfl_xor_sync(0xffffffffu, sum0, 2);
    sum1 += __shfl_xor_sync(0xffffffffu, sum1, 1);
    sum1 += __shfl_xor_sync(0xffffffffu, sum1, 2);
    const float inv0 = 1.0f / sum0;
    const float inv1 = 1.0f / sum1;

    // P -> A fragment (fp16): a0=(gid, j lo), a1=(gid+8, j lo), a2/a3 = j hi
    uint32_t aP[4];
    {
        __half2 h;
        h = __floats2half2_rn(e00 * inv0, e01 * inv0); aP[0] = *(uint32_t*)&h;
        h = __floats2half2_rn(e02 * inv1, e03 * inv1); aP[1] = *(uint32_t*)&h;
        h = __floats2half2_rn(e10 * inv0, e11 * inv0); aP[2] = *(uint32_t*)&h;
        h = __floats2half2_rn(e12 * inv1, e13 * inv1); aP[3] = *(uint32_t*)&h;
    }

    // ---- O = P V  (8 n-tiles of 8 dims; k = 16 j's; V via ldmatrix.trans)
    float o[8][4];
    #pragma unroll
    for (int i = 0; i < 8; i++)
        #pragma unroll
        for (int r = 0; r < 4; r++) o[i][r] = 0.0f;
    {
        const int jv = lane & 15;                       // V row (head j)
        const uint32_t cv = (uint32_t)(lane >> 4);      // d-half chunk
        #pragma unroll
        for (int dp = 0; dp < 4; dp++) {
            uint32_t bb[4];
            LDX4T(bb, vb + jv * 128 +
                  ((((uint32_t)(dp * 2) + cv) << 4) ^ ((jv & 7) << 4)));
            MMA16816(o[dp * 2],     aP, bb);
            MMA16816(o[dp * 2 + 1], aP, bb + 2);
        }
    }

    // ---- store O[i][d] -> g_vh[p*1024 + i*64 + d] ----
    const int gid = lane >> 2;
    const int q2  = (lane & 3) * 2;
    __half* orow = g_vh + p * (size_t)DD;
    #pragma unroll
    for (int dt = 0; dt < 8; dt++) {
        const int d0 = dt * 8 + q2;
        *reinterpret_cast<__half2*>(orow + gid * HDIM + d0) =
            __floats2half2_rn(o[dt][0], o[dt][1]);
        *reinterpret_cast<__half2*>(orow + (gid + 8) * HDIM + d0) =
            __floats2half2_rn(o[dt][2], o[dt][3]);
    }
}

// ---------------------------------------------------------------------------
// Launch: x, W_qkv, b_qkv, W_out, b_out
// ---------------------------------------------------------------------------
extern "C" void kernel_launch(void* const* d_in, const int* in_sizes, int n_in,
                              void* d_out, int out_size)
{
    const float* x     = (const float*)d_in[0];
    const float* W_qkv = (const float*)d_in[1];
    const float* b_qkv = (const float*)d_in[2];
    const float* W_out = (const float*)d_in[3];
    const float* b_out = (const float*)d_in[4];
    float* out = (float*)d_out;

    __half *qkvh, *xh, *wq, *wo, *vh;
    cudaGetSymbolAddress((void**)&qkvh, g_qkvh);
    cudaGetSymbolAddress((void**)&xh, g_xh);
    cudaGetSymbolAddress((void**)&wq, g_wq);
    cudaGetSymbolAddress((void**)&wo, g_wo);
    cudaGetSymbolAddress((void**)&vh, g_vh);

    cudaFuncSetAttribute(gemm_hmma<__half>,
                         cudaFuncAttributeMaxDynamicSharedMemorySize, SMEM_DYN);
    cudaFuncSetAttribute(gemm_hmma<float>,
                         cudaFuncAttributeMaxDynamicSharedMemorySize, SMEM_DYN);

    // conversions
    conv_h<<<(size_t)MM * DD / (256 * 4), 256>>>(x, xh);
    transpose_h<<<dim3(KK / 32, N_QKV / 32), dim3(32, 8)>>>(W_qkv, wq, N_QKV);
    transpose_h<<<dim3(KK / 32, DD / 32), dim3(32, 8)>>>(W_out, wo, DD);

    // GEMM1: qkv(fp16) = x @ W_qkv + b_qkv   (32768 x 3072, K=1024)
    gemm_hmma<__half><<<dim3(N_QKV / BN, MM / BM), 256, SMEM_DYN>>>(
        xh, wq, b_qkv, qkvh, N_QKV);

    // attention: one warp per token, 8 tokens per block
    attn_kernel<<<MM / 8, 256>>>();

    // GEMM2: out = val @ W_out + b_out (32768 x 1024, K=1024)
    gemm_hmma<float><<<dim3(DD / BN, MM / BM), 256, SMEM_DYN>>>(
        vh, wo, b_out, out, DD);
}

// round 15
// speedup vs baseline: 1.8133x; 1.0164x over previous
#include <cuda_runtime.h>
#include <cuda_fp16.h>
#include <cstdint>
#include <math.h>

// Problem: B=8, S=4096, D=1024, H=16, hd=64
#define MM 32768          // B*S
#define DD 1024
#define N_QKV 3072
#define NHEAD 16
#define HDIM 64
#define KK 1024

// GEMM tiling: single-pass fp16 (CTA 128x128, warp 64x32) — committed R10/R14
#define BM 128
#define BN 128
#define BK 64
#define NCHUNK (KK / BK)      // 16
#define NSTAGE 3

#define OFF_A 0
#define OFF_B 16384
#define BUF_BYTES 32768
#define SMEM_DYN (NSTAGE * BUF_BYTES)     // 96 KB -> 2 CTAs/SM

// attention: 4 warps/block, 4 tokens/warp, double-buffered staging
#define AT_WARPS 4
#define AT_TPW 4
#define AT_BUF_B (3 * 2048 + 64)          // q|k|v (2KB each) + 64B pad = 6208
#define AT_SMEM (AT_WARPS * 2 * AT_BUF_B) // 49664 B dynamic

// ---------------------------------------------------------------------------
// Scratch (device globals)
// ---------------------------------------------------------------------------
__device__ __half g_qkvh[(size_t)MM * N_QKV];   // fp16 qkv
__device__ __half g_xh[(size_t)MM * DD];
__device__ __half g_wq[(size_t)N_QKV * KK];     // W_qkv^T  [N][K] fp16
__device__ __half g_wo[(size_t)DD * KK];        // W_out^T
__device__ __half g_vh[(size_t)MM * DD];

// ---------------------------------------------------------------------------
// Helpers
// ---------------------------------------------------------------------------
__device__ __forceinline__ uint32_t smem_u32(const void* p) {
    uint32_t a;
    asm("{ .reg .u64 t; cvta.to.shared.u64 t, %1; cvt.u32.u64 %0, t; }"
        : "=r"(a) : "l"(p));
    return a;
}

__device__ __forceinline__ void cp16(uint32_t dst, const void* src) {
    asm volatile("cp.async.cg.shared.global [%0], [%1], 16;"
                 :: "r"(dst), "l"(src) : "memory");
}
__device__ __forceinline__ void cp_commit() {
    asm volatile("cp.async.commit_group;" ::: "memory");
}
template <int N>
__device__ __forceinline__ void cp_wait() {
    asm volatile("cp.async.wait_group %0;" :: "n"(N) : "memory");
}

#define LDX4(r, addr) \
    asm volatile("ldmatrix.sync.aligned.m8n8.x4.shared.b16 {%0,%1,%2,%3}, [%4];" \
        : "=r"((r)[0]), "=r"((r)[1]), "=r"((r)[2]), "=r"((r)[3]) : "r"(addr))

#define LDX4T(r, addr) \
    asm volatile("ldmatrix.sync.aligned.m8n8.x4.trans.shared.b16 {%0,%1,%2,%3}, [%4];" \
        : "=r"((r)[0]), "=r"((r)[1]), "=r"((r)[2]), "=r"((r)[3]) : "r"(addr))

#define MMA16816(d, a, b) \
    asm volatile("mma.sync.aligned.m16n8k16.row.col.f32.f16.f16.f32 " \
        "{%0,%1,%2,%3}, {%4,%5,%6,%7}, {%8,%9}, {%0,%1,%2,%3};" \
        : "+f"((d)[0]), "+f"((d)[1]), "+f"((d)[2]), "+f"((d)[3]) \
        : "r"((a)[0]), "r"((a)[1]), "r"((a)[2]), "r"((a)[3]), \
          "r"((b)[0]), "r"((b)[1]))

// ---------------------------------------------------------------------------
// HMMA GEMM (single-pass fp16): C[M,Ntot] = A[M,K] @ B[Ntot,K]^T + bias
// fp32 accum, OutT output. CTA 128x128, warp 64x32 (2m x 4n), BK=64, SW128,
// 3-stage cp.async, 2 CTAs/SM, ONE __syncthreads per chunk. (committed)
// ---------------------------------------------------------------------------
template <typename OutT>
__global__ __launch_bounds__(256, 2)
void gemm_hmma(const __half* __restrict__ Am, const __half* __restrict__ Bm,
               const float* __restrict__ bias, OutT* __restrict__ C, int Ntot)
{
    extern __shared__ char smem[];
    const uint32_t sb = smem_u32(smem);

    const int tid  = threadIdx.x;
    const int wid  = tid >> 5;
    const int lane = tid & 31;
    const int wm = (wid & 1) * 64;
    const int wn = (wid >> 1) * 32;

    const size_t m0 = (size_t)blockIdx.y * BM;
    const size_t n0 = (size_t)blockIdx.x * BN;

    const __half* srcA[4];
    const __half* srcB[4];
    uint32_t dstOff[4];
    #pragma unroll
    for (int t = 0; t < 4; t++) {
        int idx = tid + t * 256;
        int row = idx >> 3;
        int cq  = idx & 7;
        srcA[t] = Am + (m0 + row) * KK + cq * 8;
        srcB[t] = Bm + (n0 + row) * KK + cq * 8;
        dstOff[t] = row * 128 + ((cq * 16) ^ ((row & 7) << 4));   // SW128
    }

    uint32_t offA[4], offB[2];
    #pragma unroll
    for (int tm = 0; tm < 4; tm++) {
        int row = wm + tm * 16 + (lane & 15);
        offA[tm] = row * 128 + ((((lane >> 4) << 4)) ^ ((row & 7) << 4));
    }
    #pragma unroll
    for (int tp = 0; tp < 2; tp++) {
        int row = wn + tp * 16 + ((lane >> 4) & 1) * 8 + (lane & 7);
        offB[tp] = row * 128 + ((((lane >> 3) & 1) * 16) ^ ((row & 7) << 4));
    }

    float acc[4][4][4];
    #pragma unroll
    for (int i = 0; i < 4; i++)
        #pragma unroll
        for (int j = 0; j < 4; j++)
            #pragma unroll
            for (int r = 0; r < 4; r++) acc[i][j][r] = 0.0f;

    #pragma unroll
    for (int s = 0; s < 2; s++) {
        const uint32_t buf = sb + s * BUF_BYTES;
        const int koff = s * BK;
        #pragma unroll
        for (int t = 0; t < 4; t++) {
            cp16(buf + OFF_A + dstOff[t], srcA[t] + koff);
            cp16(buf + OFF_B + dstOff[t], srcB[t] + koff);
        }
        cp_commit();
    }

    int bufIdx = 0;
    #pragma unroll 1
    for (int c = 0; c < NCHUNK; ++c) {
        cp_wait<1>();
        __syncthreads();

        if (c + 2 < NCHUNK) {
            int pidx = bufIdx + 2; if (pidx >= NSTAGE) pidx -= NSTAGE;
            const uint32_t nbuf = sb + pidx * BUF_BYTES;
            const int koff = (c + 2) * BK;
            #pragma unroll
            for (int t = 0; t < 4; t++) {
                cp16(nbuf + OFF_A + dstOff[t], srcA[t] + koff);
                cp16(nbuf + OFF_B + dstOff[t], srcB[t] + koff);
            }
        }
        cp_commit();

        const uint32_t buf = sb + bufIdx * BUF_BYTES;
        #pragma unroll
        for (int ks = 0; ks < 4; ks++) {
            const uint32_t kx = ks * 32;
            uint32_t aa[4][4], bb[4][2];

            #pragma unroll
            for (int tm = 0; tm < 4; tm++)
                LDX4(aa[tm], buf + OFF_A + (offA[tm] ^ kx));
            #pragma unroll
            for (int tp = 0; tp < 2; tp++) {
                uint32_t r[4];
                LDX4(r, buf + OFF_B + (offB[tp] ^ kx));
                bb[2 * tp][0] = r[0]; bb[2 * tp][1] = r[1];
                bb[2 * tp + 1][0] = r[2]; bb[2 * tp + 1][1] = r[3];
            }
            #pragma unroll
            for (int tm = 0; tm < 4; tm++)
                #pragma unroll
                for (int tn = 0; tn < 4; tn++)
                    MMA16816(acc[tm][tn], aa[tm], bb[tn]);
        }
        if (++bufIdx == NSTAGE) bufIdx = 0;
    }

    const int rq = lane >> 2;
    const int cp = (lane & 3) * 2;
    #pragma unroll
    for (int tn = 0; tn < 4; tn++) {
        const int col = (int)n0 + wn + tn * 8 + cp;
        const float b0 = bias[col], b1 = bias[col + 1];
        #pragma unroll
        for (int tm = 0; tm < 4; tm++) {
            const size_t r1 = m0 + wm + tm * 16 + rq;
            float2 o0, o1;
            o0.x = acc[tm][tn][0] + b0;
            o0.y = acc[tm][tn][1] + b1;
            o1.x = acc[tm][tn][2] + b0;
            o1.y = acc[tm][tn][3] + b1;
            if constexpr (sizeof(OutT) == 4) {
                *reinterpret_cast<float2*>((float*)C + r1 * Ntot + col) = o0;
                *reinterpret_cast<float2*>((float*)C + (r1 + 8) * Ntot + col) = o1;
            } else {
                *reinterpret_cast<__half2*>((__half*)C + r1 * Ntot + col) =
                    __floats2half2_rn(o0.x, o0.y);
                *reinterpret_cast<__half2*>((__half*)C + (r1 + 8) * Ntot + col) =
                    __floats2half2_rn(o1.x, o1.y);
            }
        }
    }
}

// ---------------------------------------------------------------------------
// fp32 -> fp16 convert (x)
// ---------------------------------------------------------------------------
__global__ __launch_bounds__(256)
void conv_h(const float* __restrict__ in, __half* __restrict__ hi)
{
    size_t i0 = ((size_t)blockIdx.x * 256 + threadIdx.x) * 4;
    float4 v = *reinterpret_cast<const float4*>(in + i0);
    __half2 a, b;
    a.x = __float2half_rn(v.x); a.y = __float2half_rn(v.y);
    b.x = __float2half_rn(v.z); b.y = __float2half_rn(v.w);
    reinterpret_cast<__half2*>(hi + i0)[0] = a;
    reinterpret_cast<__half2*>(hi + i0)[1] = b;
}

// ---------------------------------------------------------------------------
// W[K][N] fp32 -> W^T[N][K] fp16, tiled & coalesced
// ---------------------------------------------------------------------------
__global__ __launch_bounds__(256)
void transpose_h(const float* __restrict__ W, __half* __restrict__ WT, int N)
{
    __shared__ float tile[32][33];
    const int k0 = blockIdx.x * 32;
    const int n0 = blockIdx.y * 32;
    const int tx = threadIdx.x, ty = threadIdx.y;
    #pragma unroll
    for (int j = 0; j < 4; j++)
        tile[ty + j * 8][tx] = W[(size_t)(k0 + ty + j * 8) * N + n0 + tx];
    __syncthreads();
    #pragma unroll
    for (int j = 0; j < 4; j++)
        WT[(size_t)(n0 + ty + j * 8) * KK + k0 + tx] =
            __float2half_rn(tile[tx][ty + j * 8]);
}

// ---------------------------------------------------------------------------
// Per-token 16x16 head attention via tensor cores. One warp per token,
// 4 tokens/warp with DOUBLE-BUFFERED cp.async staging (ping-pong, per-warp).
// Compute path identical to R14 (S = QK^T, fragment softmax, O = PV).
// ---------------------------------------------------------------------------
__global__ __launch_bounds__(128)
void attn_kernel()
{
    extern __shared__ char dsm[];

    const int tid  = threadIdx.x;
    const int wid  = tid >> 5;
    const int lane = tid & 31;
    const size_t pbase = (size_t)blockIdx.x * (AT_WARPS * AT_TPW) + wid * AT_TPW;

    const uint32_t wb0 = smem_u32(dsm) + wid * 2 * AT_BUF_B;

    // per-lane staging map: 12 chunks of 16B each
    uint32_t stOff[12];
    const int4* srcBase[12];
    #pragma unroll
    for (int t = 0; t < 12; t++) {
        int c  = lane + t * 32;
        int h  = c / 24;                  // head
        int cc = c - h * 24;              // chunk within head
        int sec = cc >> 3;                // 0=q 1=k 2=v
        int dc  = cc & 7;                 // 16B chunk within 128B row
        stOff[t] = sec * 2048 + h * 128 + (((uint32_t)dc << 4) ^ ((h & 7) << 4));
        srcBase[t] = reinterpret_cast<const int4*>(g_qkvh + pbase * N_QKV) + c;
    }

    // prefetch token 0 into buffer 0
    #pragma unroll
    for (int t = 0; t < 12; t++)
        cp16(wb0 + stOff[t], srcBase[t]);
    cp_commit();

    #pragma unroll 1
    for (int i = 0; i < AT_TPW; ++i) {
        // prefetch token i+1 into the other buffer
        if (i + 1 < AT_TPW) {
            const uint32_t nb = wb0 + ((i + 1) & 1) * AT_BUF_B;
            const int so = (i + 1) * (N_QKV / 8);     // int4 stride per token
            #pragma unroll
            for (int t = 0; t < 12; t++)
                cp16(nb + stOff[t], srcBase[t] + so);
        }
        cp_commit();
        cp_wait<1>();
        __syncwarp();

        const uint32_t wb = wb0 + (i & 1) * AT_BUF_B;
        const uint32_t qb = wb, kb = wb + 2048, vb = wb + 4096;

        // ---- S = Q K^T ----
        float s0[4] = {0.f, 0.f, 0.f, 0.f};
        float s1[4] = {0.f, 0.f, 0.f, 0.f};
        {
            const int ia = lane & 15;
            const uint32_t ca = (uint32_t)(lane >> 4);
            const int jb = (lane & 7) + ((lane >> 4) << 3);
            const uint32_t cb = (uint32_t)((lane >> 3) & 1);
            #pragma unroll
            for (int kc = 0; kc < 4; kc++) {
                uint32_t aa[4], bb[4];
                LDX4(aa, qb + ia * 128 +
                     ((((uint32_t)(kc * 2) + ca) << 4) ^ ((ia & 7) << 4)));
                LDX4(bb, kb + jb * 128 +
                     ((((uint32_t)(kc * 2) + cb) << 4) ^ ((jb & 7) << 4)));
                MMA16816(s0, aa, bb);
                MMA16816(s1, aa, bb + 2);
            }
        }

        // ---- fragment softmax ----
        #pragma unroll
        for (int r = 0; r < 4; r++) { s0[r] *= 0.125f; s1[r] *= 0.125f; }

        float m0 = fmaxf(fmaxf(s0[0], s0[1]), fmaxf(s1[0], s1[1]));
        float m1 = fmaxf(fmaxf(s0[2], s0[3]), fmaxf(s1[2], s1[3]));
        m0 = fmaxf(m0, __shfl_xor_sync(0xffffffffu, m0, 1));
        m0 = fmaxf(m0, __shfl_xor_sync(0xffffffffu, m0, 2));
        m1 = fmaxf(m1, __shfl_xor_sync(0xffffffffu, m1, 1));
        m1 = fmaxf(m1, __shfl_xor_sync(0xffffffffu, m1, 2));

        float e00 = __expf(s0[0] - m0), e01 = __expf(s0[1] - m0);
        float e10 = __expf(s1[0] - m0), e11 = __expf(s1[1] - m0);
        float e02 = __expf(s0[2] - m1), e03 = __expf(s0[3] - m1);
        float e12 = __expf(s1[2] - m1), e13 = __expf(s1[3] - m1);

        float sum0 = e00 + e01 + e10 + e11;
        float sum1 = e02 + e03 + e12 + e13;
        sum0 += __shfl_xor_sync(0xffffffffu, sum0, 1);
        sum0 += __shfl_xor_sync(0xffffffffu, sum0, 2);
        sum1 += __shfl_xor_sync(0xffffffffu, sum1, 1);
        sum1 += __shfl_xor_sync(0xffffffffu, sum1, 2);
        const float inv0 = 1.0f / sum0;
        const float inv1 = 1.0f / sum1;

        uint32_t aP[4];
        {
            __half2 h;
            h = __floats2half2_rn(e00 * inv0, e01 * inv0); aP[0] = *(uint32_t*)&h;
            h = __floats2half2_rn(e02 * inv1, e03 * inv1); aP[1] = *(uint32_t*)&h;
            h = __floats2half2_rn(e10 * inv0, e11 * inv0); aP[2] = *(uint32_t*)&h;
            h = __floats2half2_rn(e12 * inv1, e13 * inv1); aP[3] = *(uint32_t*)&h;
        }

        // ---- O = P V ----
        float o[8][4];
        #pragma unroll
        for (int q = 0; q < 8; q++)
            #pragma unroll
            for (int r = 0; r < 4; r++) o[q][r] = 0.0f;
        {
            const int jv = lane & 15;
            const uint32_t cv = (uint32_t)(lane >> 4);
            #pragma unroll
            for (int dp = 0; dp < 4; dp++) {
                uint32_t bb[4];
                LDX4T(bb, vb + jv * 128 +
                      ((((uint32_t)(dp * 2) + cv) << 4) ^ ((jv & 7) << 4)));
                MMA16816(o[dp * 2],     aP, bb);
                MMA16816(o[dp * 2 + 1], aP, bb + 2);
            }
        }

        // ---- store ----
        const int gid = lane >> 2;
        const int q2  = (lane & 3) * 2;
        __half* orow = g_vh + (pbase + i) * (size_t)DD;
        #pragma unroll
        for (int dt = 0; dt < 8; dt++) {
            const int d0 = dt * 8 + q2;
            *reinterpret_cast<__half2*>(orow + gid * HDIM + d0) =
                __floats2half2_rn(o[dt][0], o[dt][1]);
            *reinterpret_cast<__half2*>(orow + (gid + 8) * HDIM + d0) =
                __floats2half2_rn(o[dt][2], o[dt][3]);
        }
        __syncwarp();   // buffer (i&1) must be fully read before iter i+2 reuses it
    }
}

// ---------------------------------------------------------------------------
// Launch: x, W_qkv, b_qkv, W_out, b_out
// ---------------------------------------------------------------------------
extern "C" void kernel_launch(void* const* d_in, const int* in_sizes, int n_in,
                              void* d_out, int out_size)
{
    const float* x     = (const float*)d_in[0];
    const float* W_qkv = (const float*)d_in[1];
    const float* b_qkv = (const float*)d_in[2];
    const float* W_out = (const float*)d_in[3];
    const float* b_out = (const float*)d_in[4];
    float* out = (float*)d_out;

    __half *qkvh, *xh, *wq, *wo, *vh;
    cudaGetSymbolAddress((void**)&qkvh, g_qkvh);
    cudaGetSymbolAddress((void**)&xh, g_xh);
    cudaGetSymbolAddress((void**)&wq, g_wq);
    cudaGetSymbolAddress((void**)&wo, g_wo);
    cudaGetSymbolAddress((void**)&vh, g_vh);

    cudaFuncSetAttribute(gemm_hmma<__half>,
                         cudaFuncAttributeMaxDynamicSharedMemorySize, SMEM_DYN);
    cudaFuncSetAttribute(gemm_hmma<float>,
                         cudaFuncAttributeMaxDynamicSharedMemorySize, SMEM_DYN);
    cudaFuncSetAttribute(attn_kernel,
                         cudaFuncAttributeMaxDynamicSharedMemorySize, AT_SMEM);

    // conversions
    conv_h<<<(size_t)MM * DD / (256 * 4), 256>>>(x, xh);
    transpose_h<<<dim3(KK / 32, N_QKV / 32), dim3(32, 8)>>>(W_qkv, wq, N_QKV);
    transpose_h<<<dim3(KK / 32, DD / 32), dim3(32, 8)>>>(W_out, wo, DD);

    // GEMM1: qkv(fp16) = x @ W_qkv + b_qkv   (32768 x 3072, K=1024)
    gemm_hmma<__half><<<dim3(N_QKV / BN, MM / BM), 256, SMEM_DYN>>>(
        xh, wq, b_qkv, qkvh, N_QKV);

    // attention: 4 warps/block, 4 tokens/warp, double-buffered staging
    attn_kernel<<<MM / (AT_WARPS * AT_TPW), 128, AT_SMEM>>>();

    // GEMM2: out = val @ W_out + b_out (32768 x 1024, K=1024)
    gemm_hmma<float><<<dim3(DD / BN, MM / BM), 256, SMEM_DYN>>>(
        vh, wo, b_out, out, DD);
}

// round 17
// speedup vs baseline: 1.8169x; 1.0020x over previous
#include <cuda_runtime.h>
#include <cuda_fp16.h>
#include <cstdint>
#include <math.h>

// Problem: B=8, S=4096, D=1024, H=16, hd=64
#define MM 32768          // B*S
#define DD 1024
#define N_QKV 3072
#define NHEAD 16
#define HDIM 64
#define KK 1024

// GEMM tiling: single-pass fp16 (CTA 128x128, warp 64x32) — committed
#define BM 128
#define BN 128
#define BK 64
#define NCHUNK (KK / BK)      // 16
#define NSTAGE 3

#define OFF_A 0
#define OFF_B 16384
#define BUF_BYTES 32768
#define SMEM_DYN (NSTAGE * BUF_BYTES)     // 96 KB -> 2 CTAs/SM

// attention: 4 warps/block, 8 tokens/warp, double-buffered staging
#define AT_WARPS 4
#define AT_TPW 8
#define AT_BUF_B (3 * 2048 + 64)          // q|k|v (2KB each) + 64B pad = 6208
#define AT_SMEM (AT_WARPS * 2 * AT_BUF_B) // 49664 B dynamic

// ---------------------------------------------------------------------------
// Scratch (device globals)
// ---------------------------------------------------------------------------
__device__ __half g_qkvh[(size_t)MM * N_QKV];   // fp16 qkv
__device__ __half g_xh[(size_t)MM * DD];
__device__ __half g_wq[(size_t)N_QKV * KK];     // W_qkv^T  [N][K] fp16
__device__ __half g_wo[(size_t)DD * KK];        // W_out^T
__device__ __half g_vh[(size_t)MM * DD];

// ---------------------------------------------------------------------------
// Helpers
// ---------------------------------------------------------------------------
__device__ __forceinline__ uint32_t smem_u32(const void* p) {
    uint32_t a;
    asm("{ .reg .u64 t; cvta.to.shared.u64 t, %1; cvt.u32.u64 %0, t; }"
        : "=r"(a) : "l"(p));
    return a;
}

__device__ __forceinline__ void cp16(uint32_t dst, const void* src) {
    asm volatile("cp.async.cg.shared.global [%0], [%1], 16;"
                 :: "r"(dst), "l"(src) : "memory");
}
__device__ __forceinline__ void cp_commit() {
    asm volatile("cp.async.commit_group;" ::: "memory");
}
template <int N>
__device__ __forceinline__ void cp_wait() {
    asm volatile("cp.async.wait_group %0;" :: "n"(N) : "memory");
}

#define LDX4(r, addr) \
    asm volatile("ldmatrix.sync.aligned.m8n8.x4.shared.b16 {%0,%1,%2,%3}, [%4];" \
        : "=r"((r)[0]), "=r"((r)[1]), "=r"((r)[2]), "=r"((r)[3]) : "r"(addr))

#define LDX4T(r, addr) \
    asm volatile("ldmatrix.sync.aligned.m8n8.x4.trans.shared.b16 {%0,%1,%2,%3}, [%4];" \
        : "=r"((r)[0]), "=r"((r)[1]), "=r"((r)[2]), "=r"((r)[3]) : "r"(addr))

#define MMA16816(d, a, b) \
    asm volatile("mma.sync.aligned.m16n8k16.row.col.f32.f16.f16.f32 " \
        "{%0,%1,%2,%3}, {%4,%5,%6,%7}, {%8,%9}, {%0,%1,%2,%3};" \
        : "+f"((d)[0]), "+f"((d)[1]), "+f"((d)[2]), "+f"((d)[3]) \
        : "r"((a)[0]), "r"((a)[1]), "r"((a)[2]), "r"((a)[3]), \
          "r"((b)[0]), "r"((b)[1]))

// ---------------------------------------------------------------------------
// HMMA GEMM (single-pass fp16): C[M,Ntot] = A[M,K] @ B[Ntot,K]^T + bias
// fp32 accum, OutT output. CTA 128x128, warp 64x32 (2m x 4n), BK=64, SW128,
// 3-stage cp.async, 2 CTAs/SM, ONE __syncthreads per chunk. (committed)
// ---------------------------------------------------------------------------
template <typename OutT>
__global__ __launch_bounds__(256, 2)
void gemm_hmma(const __half* __restrict__ Am, const __half* __restrict__ Bm,
               const float* __restrict__ bias, OutT* __restrict__ C, int Ntot)
{
    extern __shared__ char smem[];
    const uint32_t sb = smem_u32(smem);

    const int tid  = threadIdx.x;
    const int wid  = tid >> 5;
    const int lane = tid & 31;
    const int wm = (wid & 1) * 64;
    const int wn = (wid >> 1) * 32;

    const size_t m0 = (size_t)blockIdx.y * BM;
    const size_t n0 = (size_t)blockIdx.x * BN;

    const __half* srcA[4];
    const __half* srcB[4];
    uint32_t dstOff[4];
    #pragma unroll
    for (int t = 0; t < 4; t++) {
        int idx = tid + t * 256;
        int row = idx >> 3;
        int cq  = idx & 7;
        srcA[t] = Am + (m0 + row) * KK + cq * 8;
        srcB[t] = Bm + (n0 + row) * KK + cq * 8;
        dstOff[t] = row * 128 + ((cq * 16) ^ ((row & 7) << 4));   // SW128
    }

    uint32_t offA[4], offB[2];
    #pragma unroll
    for (int tm = 0; tm < 4; tm++) {
        int row = wm + tm * 16 + (lane & 15);
        offA[tm] = row * 128 + ((((lane >> 4) << 4)) ^ ((row & 7) << 4));
    }
    #pragma unroll
    for (int tp = 0; tp < 2; tp++) {
        int row = wn + tp * 16 + ((lane >> 4) & 1) * 8 + (lane & 7);
        offB[tp] = row * 128 + ((((lane >> 3) & 1) * 16) ^ ((row & 7) << 4));
    }

    float acc[4][4][4];
    #pragma unroll
    for (int i = 0; i < 4; i++)
        #pragma unroll
        for (int j = 0; j < 4; j++)
            #pragma unroll
            for (int r = 0; r < 4; r++) acc[i][j][r] = 0.0f;

    #pragma unroll
    for (int s = 0; s < 2; s++) {
        const uint32_t buf = sb + s * BUF_BYTES;
        const int koff = s * BK;
        #pragma unroll
        for (int t = 0; t < 4; t++) {
            cp16(buf + OFF_A + dstOff[t], srcA[t] + koff);
            cp16(buf + OFF_B + dstOff[t], srcB[t] + koff);
        }
        cp_commit();
    }

    int bufIdx = 0;
    #pragma unroll 1
    for (int c = 0; c < NCHUNK; ++c) {
        cp_wait<1>();
        __syncthreads();

        if (c + 2 < NCHUNK) {
            int pidx = bufIdx + 2; if (pidx >= NSTAGE) pidx -= NSTAGE;
            const uint32_t nbuf = sb + pidx * BUF_BYTES;
            const int koff = (c + 2) * BK;
            #pragma unroll
            for (int t = 0; t < 4; t++) {
                cp16(nbuf + OFF_A + dstOff[t], srcA[t] + koff);
                cp16(nbuf + OFF_B + dstOff[t], srcB[t] + koff);
            }
        }
        cp_commit();

        const uint32_t buf = sb + bufIdx * BUF_BYTES;
        #pragma unroll
        for (int ks = 0; ks < 4; ks++) {
            const uint32_t kx = ks * 32;
            uint32_t aa[4][4], bb[4][2];

            #pragma unroll
            for (int tm = 0; tm < 4; tm++)
                LDX4(aa[tm], buf + OFF_A + (offA[tm] ^ kx));
            #pragma unroll
            for (int tp = 0; tp < 2; tp++) {
                uint32_t r[4];
                LDX4(r, buf + OFF_B + (offB[tp] ^ kx));
                bb[2 * tp][0] = r[0]; bb[2 * tp][1] = r[1];
                bb[2 * tp + 1][0] = r[2]; bb[2 * tp + 1][1] = r[3];
            }
            #pragma unroll
            for (int tm = 0; tm < 4; tm++)
                #pragma unroll
                for (int tn = 0; tn < 4; tn++)
                    MMA16816(acc[tm][tn], aa[tm], bb[tn]);
        }
        if (++bufIdx == NSTAGE) bufIdx = 0;
    }

    const int rq = lane >> 2;
    const int cp = (lane & 3) * 2;
    #pragma unroll
    for (int tn = 0; tn < 4; tn++) {
        const int col = (int)n0 + wn + tn * 8 + cp;
        const float b0 = bias[col], b1 = bias[col + 1];
        #pragma unroll
        for (int tm = 0; tm < 4; tm++) {
            const size_t r1 = m0 + wm + tm * 16 + rq;
            float2 o0, o1;
            o0.x = acc[tm][tn][0] + b0;
            o0.y = acc[tm][tn][1] + b1;
            o1.x = acc[tm][tn][2] + b0;
            o1.y = acc[tm][tn][3] + b1;
            if constexpr (sizeof(OutT) == 4) {
                *reinterpret_cast<float2*>((float*)C + r1 * Ntot + col) = o0;
                *reinterpret_cast<float2*>((float*)C + (r1 + 8) * Ntot + col) = o1;
            } else {
                *reinterpret_cast<__half2*>((__half*)C + r1 * Ntot + col) =
                    __floats2half2_rn(o0.x, o0.y);
                *reinterpret_cast<__half2*>((__half*)C + (r1 + 8) * Ntot + col) =
                    __floats2half2_rn(o1.x, o1.y);
            }
        }
    }
}

// ---------------------------------------------------------------------------
// fp32 -> fp16 convert (x)
// ---------------------------------------------------------------------------
__global__ __launch_bounds__(256)
void conv_h(const float* __restrict__ in, __half* __restrict__ hi)
{
    size_t i0 = ((size_t)blockIdx.x * 256 + threadIdx.x) * 4;
    float4 v = *reinterpret_cast<const float4*>(in + i0);
    __half2 a, b;
    a.x = __float2half_rn(v.x); a.y = __float2half_rn(v.y);
    b.x = __float2half_rn(v.z); b.y = __float2half_rn(v.w);
    reinterpret_cast<__half2*>(hi + i0)[0] = a;
    reinterpret_cast<__half2*>(hi + i0)[1] = b;
}

// ---------------------------------------------------------------------------
// Fused weight transpose: W_qkv[K][3072] -> wq[3072][K] and
// W_out[K][1024] -> wo[1024][K], one launch. blockIdx.y selects column tile:
// tiles 0..95 -> W_qkv, tiles 96..127 -> W_out.
// ---------------------------------------------------------------------------
__global__ __launch_bounds__(256)
void transpose_both(const float* __restrict__ Wq, const float* __restrict__ Wo,
                    __half* __restrict__ wqT, __half* __restrict__ woT)
{
    __shared__ float tile[32][33];
    const int k0 = blockIdx.x * 32;
    const bool isQ = blockIdx.y < (N_QKV / 32);
    const int n0 = (isQ ? blockIdx.y : blockIdx.y - N_QKV / 32) * 32;
    const float* W = isQ ? Wq : Wo;
    __half* WT = isQ ? wqT : woT;
    const int N = isQ ? N_QKV : DD;

    const int tx = threadIdx.x, ty = threadIdx.y;
    #pragma unroll
    for (int j = 0; j < 4; j++)
        tile[ty + j * 8][tx] = W[(size_t)(k0 + ty + j * 8) * N + n0 + tx];
    __syncthreads();
    #pragma unroll
    for (int j = 0; j < 4; j++)
        WT[(size_t)(n0 + ty + j * 8) * KK + k0 + tx] =
            __float2half_rn(tile[tx][ty + j * 8]);
}

// ---------------------------------------------------------------------------
// Per-token 16x16 head attention via tensor cores. One warp per token,
// 8 tokens/warp with double-buffered cp.async staging (ping-pong, per-warp).
// Compute path identical to R14/R15.
// ---------------------------------------------------------------------------
__global__ __launch_bounds__(128)
void attn_kernel()
{
    extern __shared__ char dsm[];

    const int tid  = threadIdx.x;
    const int wid  = tid >> 5;
    const int lane = tid & 31;
    const size_t pbase = (size_t)blockIdx.x * (AT_WARPS * AT_TPW) + wid * AT_TPW;

    const uint32_t wb0 = smem_u32(dsm) + wid * 2 * AT_BUF_B;

    // per-lane staging map: 12 chunks of 16B each
    uint32_t stOff[12];
    const int4* srcBase[12];
    #pragma unroll
    for (int t = 0; t < 12; t++) {
        int c  = lane + t * 32;
        int h  = c / 24;                  // head
        int cc = c - h * 24;              // chunk within head
        int sec = cc >> 3;                // 0=q 1=k 2=v
        int dc  = cc & 7;                 // 16B chunk within 128B row
        stOff[t] = sec * 2048 + h * 128 + (((uint32_t)dc << 4) ^ ((h & 7) << 4));
        srcBase[t] = reinterpret_cast<const int4*>(g_qkvh + pbase * N_QKV) + c;
    }

    // prefetch token 0 into buffer 0
    #pragma unroll
    for (int t = 0; t < 12; t++)
        cp16(wb0 + stOff[t], srcBase[t]);
    cp_commit();

    #pragma unroll 1
    for (int i = 0; i < AT_TPW; ++i) {
        // prefetch token i+1 into the other buffer
        if (i + 1 < AT_TPW) {
            const uint32_t nb = wb0 + ((i + 1) & 1) * AT_BUF_B;
            const int so = (i + 1) * (N_QKV / 8);     // int4 stride per token
            #pragma unroll
            for (int t = 0; t < 12; t++)
                cp16(nb + stOff[t], srcBase[t] + so);
        }
        cp_commit();
        cp_wait<1>();
        __syncwarp();

        const uint32_t wb = wb0 + (i & 1) * AT_BUF_B;
        const uint32_t qb = wb, kb = wb + 2048, vb = wb + 4096;

        // ---- S = Q K^T ----
        float s0[4] = {0.f, 0.f, 0.f, 0.f};
        float s1[4] = {0.f, 0.f, 0.f, 0.f};
        {
            const int ia = lane & 15;
            const uint32_t ca = (uint32_t)(lane >> 4);
            const int jb = (lane & 7) + ((lane >> 4) << 3);
            const uint32_t cb = (uint32_t)((lane >> 3) & 1);
            #pragma unroll
            for (int kc = 0; kc < 4; kc++) {
                uint32_t aa[4], bb[4];
                LDX4(aa, qb + ia * 128 +
                     ((((uint32_t)(kc * 2) + ca) << 4) ^ ((ia & 7) << 4)));
                LDX4(bb, kb + jb * 128 +
                     ((((uint32_t)(kc * 2) + cb) << 4) ^ ((jb & 7) << 4)));
                MMA16816(s0, aa, bb);
                MMA16816(s1, aa, bb + 2);
            }
        }

        // ---- fragment softmax ----
        #pragma unroll
        for (int r = 0; r < 4; r++) { s0[r] *= 0.125f; s1[r] *= 0.125f; }

        float m0 = fmaxf(fmaxf(s0[0], s0[1]), fmaxf(s1[0], s1[1]));
        float m1 = fmaxf(fmaxf(s0[2], s0[3]), fmaxf(s1[2], s1[3]));
        m0 = fmaxf(m0, __shfl_xor_sync(0xffffffffu, m0, 1));
        m0 = fmaxf(m0, __shfl_xor_sync(0xffffffffu, m0, 2));
        m1 = fmaxf(m1, __shfl_xor_sync(0xffffffffu, m1, 1));
        m1 = fmaxf(m1, __shfl_xor_sync(0xffffffffu, m1, 2));

        float e00 = __expf(s0[0] - m0), e01 = __expf(s0[1] - m0);
        float e10 = __expf(s1[0] - m0), e11 = __expf(s1[1] - m0);
        float e02 = __expf(s0[2] - m1), e03 = __expf(s0[3] - m1);
        float e12 = __expf(s1[2] - m1), e13 = __expf(s1[3] - m1);

        float sum0 = e00 + e01 + e10 + e11;
        float sum1 = e02 + e03 + e12 + e13;
        sum0 += __shfl_xor_sync(0xffffffffu, sum0, 1);
        sum0 += __shfl_xor_sync(0xffffffffu, sum0, 2);
        sum1 += __shfl_xor_sync(0xffffffffu, sum1, 1);
        sum1 += __shfl_xor_sync(0xffffffffu, sum1, 2);
        const float inv0 = 1.0f / sum0;
        const float inv1 = 1.0f / sum1;

        uint32_t aP[4];
        {
            __half2 h;
            h = __floats2half2_rn(e00 * inv0, e01 * inv0); aP[0] = *(uint32_t*)&h;
            h = __floats2half2_rn(e02 * inv1, e03 * inv1); aP[1] = *(uint32_t*)&h;
            h = __floats2half2_rn(e10 * inv0, e11 * inv0); aP[2] = *(uint32_t*)&h;
            h = __floats2half2_rn(e12 * inv1, e13 * inv1); aP[3] = *(uint32_t*)&h;
        }

        // ---- O = P V ----
        float o[8][4];
        #pragma unroll
        for (int q = 0; q < 8; q++)
            #pragma unroll
            for (int r = 0; r < 4; r++) o[q][r] = 0.0f;
        {
            const int jv = lane & 15;
            const uint32_t cv = (uint32_t)(lane >> 4);
            #pragma unroll
            for (int dp = 0; dp < 4; dp++) {
                uint32_t bb[4];
                LDX4T(bb, vb + jv * 128 +
                      ((((uint32_t)(dp * 2) + cv) << 4) ^ ((jv & 7) << 4)));
                MMA16816(o[dp * 2],     aP, bb);
                MMA16816(o[dp * 2 + 1], aP, bb + 2);
            }
        }

        // ---- store ----
        const int gid = lane >> 2;
        const int q2  = (lane & 3) * 2;
        __half* orow = g_vh + (pbase + i) * (size_t)DD;
        #pragma unroll
        for (int dt = 0; dt < 8; dt++) {
            const int d0 = dt * 8 + q2;
            *reinterpret_cast<__half2*>(orow + gid * HDIM + d0) =
                __floats2half2_rn(o[dt][0], o[dt][1]);
            *reinterpret_cast<__half2*>(orow + (gid + 8) * HDIM + d0) =
                __floats2half2_rn(o[dt][2], o[dt][3]);
        }
        __syncwarp();   // buffer (i&1) must be fully read before iter i+2 reuses it
    }
}

// ---------------------------------------------------------------------------
// Launch: x, W_qkv, b_qkv, W_out, b_out
// ---------------------------------------------------------------------------
extern "C" void kernel_launch(void* const* d_in, const int* in_sizes, int n_in,
                              void* d_out, int out_size)
{
    const float* x     = (const float*)d_in[0];
    const float* W_qkv = (const float*)d_in[1];
    const float* b_qkv = (const float*)d_in[2];
    const float* W_out = (const float*)d_in[3];
    const float* b_out = (const float*)d_in[4];
    float* out = (float*)d_out;

    __half *qkvh, *xh, *wq, *wo, *vh;
    cudaGetSymbolAddress((void**)&qkvh, g_qkvh);
    cudaGetSymbolAddress((void**)&xh, g_xh);
    cudaGetSymbolAddress((void**)&wq, g_wq);
    cudaGetSymbolAddress((void**)&wo, g_wo);
    cudaGetSymbolAddress((void**)&vh, g_vh);

    cudaFuncSetAttribute(gemm_hmma<__half>,
                         cudaFuncAttributeMaxDynamicSharedMemorySize, SMEM_DYN);
    cudaFuncSetAttribute(gemm_hmma<float>,
                         cudaFuncAttributeMaxDynamicSharedMemorySize, SMEM_DYN);
    cudaFuncSetAttribute(attn_kernel,
                         cudaFuncAttributeMaxDynamicSharedMemorySize, AT_SMEM);

    // conversions (weight transposes fused into one launch)
    conv_h<<<(size_t)MM * DD / (256 * 4), 256>>>(x, xh);
    transpose_both<<<dim3(KK / 32, (N_QKV + DD) / 32), dim3(32, 8)>>>(
        W_qkv, W_out, wq, wo);

    // GEMM1: qkv(fp16) = x @ W_qkv + b_qkv   (32768 x 3072, K=1024)
    gemm_hmma<__half><<<dim3(N_QKV / BN, MM / BM), 256, SMEM_DYN>>>(
        xh, wq, b_qkv, qkvh, N_QKV);

    // attention: 4 warps/block, 8 tokens/warp, double-buffered staging
    attn_kernel<<<MM / (AT_WARPS * AT_TPW), 128, AT_SMEM>>>();

    // GEMM2: out = val @ W_out + b_out (32768 x 1024, K=1024)
    gemm_hmma<float><<<dim3(DD / BN, MM / BM), 256, SMEM_DYN>>>(
        vh, wo, b_out, out, DD);
}